// round 2
// baseline (speedup 1.0000x reference)
#include <cuda_runtime.h>
#include <cstdint>

// PixelShuffle / depth-to-space, R=2, feature-major channel grouping.
//   out[b, 2x+i, 2y+j, f] = in[b, x, y, 4f + 2i + j]
// in : [B=8, X=256, Y=256, C=256] fp32
// out: [B=8, 512, 512, 64]        fp32
//
// Strategy: each thread owns 4 features (16 consecutive input channels).
// A float4 load of channels [4f, 4f+3] contains the 4 quadrant values for
// feature f, so 4 float4 loads -> register transpose -> 4 float4 stores,
// one per output quadrant. All loads and stores are full-sector.

static constexpr int B_ = 8;
static constexpr int X_ = 256;
static constexpr int Y_ = 256;
static constexpr int C_ = 256;   // = 64 features * 4
static constexpr int F4_PER_PIX_OUT = 16;   // 64 feat / 4
static constexpr int THREADS_PER_PIX = 16;  // each covers 16 input channels

__global__ __launch_bounds__(256)
void pixelshuffle_kernel(const float4* __restrict__ in, float4* __restrict__ out) {
    unsigned g = blockIdx.x * blockDim.x + threadIdx.x;
    unsigned t     = g & (THREADS_PER_PIX - 1);   // 0..15: feature-quad index
    unsigned pixel = g >> 4;                      // input pixel id, < B*X*Y

    unsigned y = pixel & (Y_ - 1);
    unsigned x = (pixel >> 8) & (X_ - 1);
    unsigned b = pixel >> 16;

    // Input: pixel row is 256 floats = 64 float4; thread t reads float4s
    // [16t/4 .. 16t/4+3] = 4 consecutive float4s (64 B).
    const float4* src = in + (size_t)pixel * (C_ / 4) + (size_t)t * 4;
    float4 v0 = src[0];   // channels 16t+0 .. 16t+3   (feature 4t+0)
    float4 v1 = src[1];   // feature 4t+1
    float4 v2 = src[2];   // feature 4t+2
    float4 v3 = src[3];   // feature 4t+3

    // Output float4 index: ((b*512 + 2x+i)*512 + 2y+j)*16 + t
    size_t ob = (((size_t)b * (2 * X_) + 2 * x) * (2 * Y_) + 2 * y) * F4_PER_PIX_OUT + t;
    const size_t ROW = (size_t)(2 * Y_) * F4_PER_PIX_OUT;  // one output row of float4s

    // component index = 2i + j selects quadrant
    out[ob]            = make_float4(v0.x, v1.x, v2.x, v3.x); // i=0, j=0
    out[ob + 16]       = make_float4(v0.y, v1.y, v2.y, v3.y); // i=0, j=1
    out[ob + ROW]      = make_float4(v0.z, v1.z, v2.z, v3.z); // i=1, j=0
    out[ob + ROW + 16] = make_float4(v0.w, v1.w, v2.w, v3.w); // i=1, j=1
}

extern "C" void kernel_launch(void* const* d_in, const int* in_sizes, int n_in,
                              void* d_out, int out_size) {
    const float4* in = (const float4*)d_in[0];
    float4* out = (float4*)d_out;

    // total threads = B*X*Y*16 = 8,388,608
    const unsigned n_threads = (unsigned)B_ * X_ * Y_ * THREADS_PER_PIX;
    const unsigned tpb = 256;
    pixelshuffle_kernel<<<n_threads / tpb, tpb>>>(in, out);
}